// round 16
// baseline (speedup 1.0000x reference)
#include <cuda_runtime.h>
#include <cuda_bf16.h>
#include <cuda_fp16.h>
#include <stdint.h>

#define BB 4
#define TT 4096
#define CC 1024
#define HH 64
#define MM (BB*TT)

// scratch (allocation-free rule -> device globals)
__device__ unsigned short g_q[MM*HH];           // fp16 q * 1/32
__device__ unsigned short g_k[MM*HH];           // fp16 k
__device__ unsigned short g_vt[BB*HH*TT];       // fp16 V^T  [b][h][t]
__device__ uint32_t g_w16[3*HH*(CC/2)];         // fp16 W^T [mat][n][k-pairs]
__device__ uint32_t g_parth[4u*MM*HH/2];        // fp16x2 split-K O partials
__device__ float g_lpart[4*MM];                 // split-K l partials

// ---------------------------------------------------------------------------
// helpers
// ---------------------------------------------------------------------------
__device__ __forceinline__ void mma16h(float* d,
    uint32_t a0, uint32_t a1, uint32_t a2, uint32_t a3, uint32_t b0, uint32_t b1) {
    asm volatile(
        "mma.sync.aligned.m16n8k16.row.col.f32.f16.f16.f32 "
        "{%0,%1,%2,%3},{%4,%5,%6,%7},{%8,%9},{%0,%1,%2,%3};"
        : "+f"(d[0]), "+f"(d[1]), "+f"(d[2]), "+f"(d[3])
        : "r"(a0), "r"(a1), "r"(a2), "r"(a3), "r"(b0), "r"(b1));
}
__device__ __forceinline__ uint32_t packh2(float lo, float hi) {  // {lo, hi}
    uint32_t r; asm("cvt.rn.f16x2.f32 %0, %1, %2;" : "=r"(r) : "f"(hi), "f"(lo));
    return r;
}
__device__ __forceinline__ uint32_t smem_u32(const void* p) {
    uint32_t a;
    asm("{ .reg .u64 t; cvta.to.shared.u64 t, %1; cvt.u32.u64 %0, t; }" : "=r"(a) : "l"(p));
    return a;
}
__device__ __forceinline__ void cp16(uint32_t dst, const void* src) {
    asm volatile("cp.async.cg.shared.global [%0], [%1], 16;" :: "r"(dst), "l"(src));
}
#define CP_COMMIT() asm volatile("cp.async.commit_group;" ::: "memory")
#define CP_WAIT1()  asm volatile("cp.async.wait_group 1;" ::: "memory")
#define CP_WAIT0()  asm volatile("cp.async.wait_group 0;" ::: "memory")

// ---------------------------------------------------------------------------
// W pre-convert: g_w16[mat][n][k2] = fp16 pair {W[2k2][n], W[2k2+1][n]}
// ---------------------------------------------------------------------------
__global__ __launch_bounds__(256) void wconv_kernel(const float* __restrict__ Wq,
                                                    const float* __restrict__ Wk,
                                                    const float* __restrict__ Wv) {
    int u = blockIdx.x * 256 + threadIdx.x;
    int k2 = u & 511, n = (u >> 9) & 63, mat = u >> 15;
    const float* W = (mat == 0) ? Wq : (mat == 1) ? Wk : Wv;
    float f0 = W[(size_t)(2*k2)*HH + n];
    float f1 = W[(size_t)(2*k2 + 1)*HH + n];
    g_w16[u] = packh2(f0, f1);
}

// ---------------------------------------------------------------------------
// Fused QKV projection, fp16 m16n8k16, 512 threads (16 warps).
// Warp (r16, ch): 16 rows x 96 cols (ch=0: q + k[0:32]; ch=1: k[32:64] + v).
// x fp32 + W fp16 both cp.async double-buffered.
// ---------------------------------------------------------------------------
#define XSTR 68
#define W16STR 36
#define QSM_X   0                              // 2 x 128*68*4 = 69632
#define QSM_W   (2*128*XSTR*4)
static const int QKV_SMEM = QSM_W + 2*192*W16STR*4;   // 124928

__device__ __forceinline__ void x_prefetch(uint32_t smb, int buf,
                                           const float* __restrict__ x,
                                           int row0, int k0g) {
    const int tid = threadIdx.x;
    const uint32_t base = smb + QSM_X + buf*(128*XSTR*4);
    #pragma unroll
    for (int it = 0; it < 4; it++) {
        int u = tid + 512*it;              // 0..2047
        int r = u >> 4, c = (u & 15) << 2;
        cp16(base + (uint32_t)(r*XSTR + c)*4, &x[(size_t)(row0 + r)*CC + k0g + c]);
    }
}
__device__ __forceinline__ void w_prefetch(uint32_t smb, int buf, int k0g) {
    const int tid = threadIdx.x;
    const uint32_t base = smb + QSM_W + buf*(192*W16STR*4);
    #pragma unroll
    for (int it = 0; it < 3; it++) {
        int u = tid + 512*it;              // 0..1535
        int r = u >> 3, q = u & 7;
        cp16(base + (uint32_t)(r*W16STR + q*4)*4,
             &g_w16[(size_t)r*512 + (k0g >> 1) + q*4]);
    }
}

__global__ __launch_bounds__(512, 1) void qkv_proj(const float* __restrict__ x) {
    extern __shared__ uint32_t smq[];
    const uint32_t smb = smem_u32(smq);

    const int tid = threadIdx.x;
    const int w = tid >> 5, lane = tid & 31, g = lane >> 2, t = lane & 3;
    const int r16 = w >> 1;            // row group 0..7 (16 rows each)
    const int ch  = w & 1;             // column half: n8-tiles [12ch, 12ch+12)
    const int row0 = blockIdx.x * 128;

    float acc[12][4];
    #pragma unroll
    for (int j = 0; j < 12; j++)
        #pragma unroll
        for (int i = 0; i < 4; i++) acc[j][i] = 0.f;

    x_prefetch(smb, 0, x, row0, 0);
    w_prefetch(smb, 0, 0);
    CP_COMMIT();

    for (int c16 = 0; c16 < 16; c16++) {
        const int k0g = c16 * 64;
        __syncthreads();
        if (c16 + 1 < 16) {
            x_prefetch(smb, (c16 + 1) & 1, x, row0, k0g + 64);
            w_prefetch(smb, (c16 + 1) & 1, k0g + 64);
            CP_COMMIT();
            CP_WAIT1();
        } else {
            CP_WAIT0();
        }
        __syncthreads();

        const float* Xr = (const float*)(smq + (QSM_X/4) + (c16 & 1)*(128*XSTR));
        const uint32_t* Ws = smq + (QSM_W/4) + (c16 & 1)*(192*W16STR);
        const int ra = (16*r16 + g)*XSTR, rb = ra + 8*XSTR;
        #pragma unroll
        for (int kk = 0; kk < 4; kk++) {
            const int k0 = kk * 16;
            float2 f00 = *(const float2*)&Xr[ra + k0 + 2*t];
            float2 f10 = *(const float2*)&Xr[rb + k0 + 2*t];
            float2 f01 = *(const float2*)&Xr[ra + k0 + 2*t + 8];
            float2 f11 = *(const float2*)&Xr[rb + k0 + 2*t + 8];
            uint32_t a0 = packh2(f00.x, f00.y), a1 = packh2(f10.x, f10.y);
            uint32_t a2 = packh2(f01.x, f01.y), a3 = packh2(f11.x, f11.y);
            #pragma unroll
            for (int j2 = 0; j2 < 12; j2++) {
                const int gj = ch*12 + j2;
                const int rq = (8*gj + g)*W16STR + 8*kk + t;
                mma16h(acc[j2], a0, a1, a2, a3, Ws[rq], Ws[rq + 4]);
            }
        }
    }

    // ---- epilogue ----
    const int lr0 = 16*r16 + g;
    const size_t r0 = (size_t)(row0 + lr0), r1 = r0 + 8;
    #pragma unroll
    for (int j2 = 0; j2 < 12; j2++) {
        const int gj = ch*12 + j2;
        if (gj < 8) {                      // q tiles (scale 1/32, exact)
            int c = gj*8 + 2*t;
            *(uint32_t*)&g_q[r0*HH + c] = packh2(acc[j2][0]*0.03125f, acc[j2][1]*0.03125f);
            *(uint32_t*)&g_q[r1*HH + c] = packh2(acc[j2][2]*0.03125f, acc[j2][3]*0.03125f);
        } else if (gj < 16) {              // k tiles
            int c = (gj - 8)*8 + 2*t;
            *(uint32_t*)&g_k[r0*HH + c] = packh2(acc[j2][0], acc[j2][1]);
            *(uint32_t*)&g_k[r1*HH + c] = packh2(acc[j2][2], acc[j2][3]);
        }
    }
    __syncthreads();
    // v staging (one fp16 bit-pattern per u32 slot), by ch=1 warps only
    uint32_t* Vstg = smq;   // x buffer area, stride 68
    if (ch == 1) {
        #pragma unroll
        for (int j2 = 4; j2 < 12; j2++) {  // gj 16..23 -> v tiles 0..7
            int c = (j2 - 4)*8 + 2*t;
            Vstg[lr0*XSTR + c]         = (uint32_t)__half_as_ushort(__float2half_rn(acc[j2][0]));
            Vstg[lr0*XSTR + c + 1]     = (uint32_t)__half_as_ushort(__float2half_rn(acc[j2][1]));
            Vstg[(lr0+8)*XSTR + c]     = (uint32_t)__half_as_ushort(__float2half_rn(acc[j2][2]));
            Vstg[(lr0+8)*XSTR + c + 1] = (uint32_t)__half_as_ushort(__float2half_rn(acc[j2][3]));
        }
    }
    __syncthreads();
    {
        int hh = tid >> 3, tp = tid & 7;
        int bB = row0 / TT, tt0 = row0 % TT;
        size_t basei = ((size_t)bB*HH + hh)*TT + tt0;
        #pragma unroll
        for (int s = 0; s < 16; s += 2) {
            int tt = tp*16 + s;
            uint32_t w0 = Vstg[tt*XSTR + hh], w1 = Vstg[(tt+1)*XSTR + hh];
            *(uint32_t*)&g_vt[basei + tt] = (w0 & 0xffffu) | (w1 << 16);
        }
    }
}

// ---------------------------------------------------------------------------
// Flash attention (round-15 engine; epilogue writes fp16-pair partials).
// ---------------------------------------------------------------------------
#define KSTR2 36
#define VTSTR 36
#define SMK   0
#define SMV   (SMK + 2*64*KSTR2*4)
#define ATTN_SMEM (SMV + 2*64*VTSTR*4)      // 36864

__device__ __forceinline__ void kv_prefetch(uint32_t smb, int buf, int b, int kt0) {
    const int tid = threadIdx.x;
    const uint32_t kb = smb + SMK + buf*(64*KSTR2*4);
    const uint32_t vb = smb + SMV + buf*(64*VTSTR*4);
    #pragma unroll
    for (int it = 0; it < 4; it++) {
        int u = tid + 128*it, r = u >> 3, q = u & 7;
        cp16(kb + (uint32_t)(r*KSTR2 + q*4)*4,
             (const char*)&g_k[((size_t)(b*TT + kt0 + r))*HH] + q*16);
    }
    #pragma unroll
    for (int it = 0; it < 4; it++) {
        int u = tid + 128*it, h = u >> 3, q = u & 7;
        cp16(vb + (uint32_t)(h*VTSTR + q*4)*4,
             (const char*)&g_vt[((size_t)(b*HH + h))*TT + kt0] + q*16);
    }
}

__global__ __launch_bounds__(128, 4) void attn_kernel() {
    extern __shared__ char sm[];
    const uint32_t smb = smem_u32(sm);
    const int tid = threadIdx.x, w = tid >> 5, lane = tid & 31;
    const int g = lane >> 2, t = lane & 3;
    const int b = blockIdx.y, e = blockIdx.x & 3, p = blockIdx.x >> 2;
    const int R0 = 16*w + g, R1 = R0 + 8;

    for (int ti = 0; ti < 2; ti++) {
        const int qt = ti ? 63 - p : p;
        const int t0 = qt * 64;
        const int n = (qt >= e) ? ((qt - e) >> 2) + 1 : 0;

        float o[8][4];
        #pragma unroll
        for (int j = 0; j < 8; j++)
            #pragma unroll
            for (int i = 0; i < 4; i++) o[j][i] = 0.f;
        float ls0 = 0.f, ls1 = 0.f;

        if (n > 0) {
            uint32_t* Pst = (uint32_t*)(sm + SMK);
            #pragma unroll
            for (int it = 0; it < 4; it++) {
                int u = tid + 128*it, r = u >> 3, q = u & 7;
                cp16(smb + SMK + (uint32_t)(r*KSTR2 + q*4)*4,
                     (const char*)&g_q[((size_t)(b*TT + t0 + r))*HH] + q*16);
            }
            CP_COMMIT(); CP_WAIT0();
            __syncthreads();
            uint32_t qa[4][4];
            #pragma unroll
            for (int kk = 0; kk < 4; kk++) {
                qa[kk][0] = Pst[R0*KSTR2 + 8*kk + t];
                qa[kk][1] = Pst[R1*KSTR2 + 8*kk + t];
                qa[kk][2] = Pst[R0*KSTR2 + 8*kk + t + 4];
                qa[kk][3] = Pst[R1*KSTR2 + 8*kk + t + 4];
            }
            __syncthreads();
            kv_prefetch(smb, 0, b, e*64);
            CP_COMMIT();

            for (int j = 0; j < n; j++) {
                const int kb = e + 4*j;
                const int kt0 = kb * 64;
                if (j + 1 < n) { kv_prefetch(smb, (j + 1) & 1, b, kt0 + 256); CP_COMMIT(); CP_WAIT1(); }
                else           { CP_WAIT0(); }
                __syncthreads();
                const uint32_t* Ks = (const uint32_t*)(sm + SMK + (j & 1)*(64*KSTR2*4));
                const uint32_t* Vs = (const uint32_t*)(sm + SMV + (j & 1)*(64*VTSTR*4));

                float s[8][4];
                #pragma unroll
                for (int jc = 0; jc < 8; jc++)
                    #pragma unroll
                    for (int i = 0; i < 4; i++) s[jc][i] = 0.f;
                #pragma unroll
                for (int kk = 0; kk < 4; kk++) {
                    #pragma unroll
                    for (int jc = 0; jc < 8; jc++)
                        mma16h(s[jc], qa[kk][0], qa[kk][1], qa[kk][2], qa[kk][3],
                               Ks[(8*jc + g)*KSTR2 + 8*kk + t],
                               Ks[(8*jc + g)*KSTR2 + 8*kk + t + 4]);
                }

                const int last = (kb == qt);
                const int r0g = t0 + R0, r1g = t0 + R1;
                #pragma unroll
                for (int kk = 0; kk < 4; kk++) {
                    uint32_t ah[4];
                    #pragma unroll
                    for (int hhh = 0; hhh < 2; hhh++) {
                        const int jc = 2*kk + hhh;
                        const int key = kt0 + 8*jc + 2*t;
                        float p00, p01, p10, p11;
                        if (last) {
                            p00 = (key     <= r0g) ? __expf(s[jc][0]) : 0.f;
                            p01 = (key + 1 <= r0g) ? __expf(s[jc][1]) : 0.f;
                            p10 = (key     <= r1g) ? __expf(s[jc][2]) : 0.f;
                            p11 = (key + 1 <= r1g) ? __expf(s[jc][3]) : 0.f;
                        } else {
                            p00 = __expf(s[jc][0]); p01 = __expf(s[jc][1]);
                            p10 = __expf(s[jc][2]); p11 = __expf(s[jc][3]);
                        }
                        ls0 += p00 + p01; ls1 += p10 + p11;
                        ah[2*hhh]     = packh2(p00, p01);
                        ah[2*hhh + 1] = packh2(p10, p11);
                    }
                    #pragma unroll
                    for (int jc = 0; jc < 8; jc++) {
                        uint32_t v0 = Vs[(8*jc + g)*VTSTR + 8*kk + t];
                        uint32_t v1 = Vs[(8*jc + g)*VTSTR + 8*kk + t + 4];
                        mma16h(o[jc], ah[0], ah[1], ah[2], ah[3], v0, v1);
                    }
                }
                __syncthreads();
            }
        }

        ls0 += __shfl_xor_sync(0xffffffffu, ls0, 1);
        ls0 += __shfl_xor_sync(0xffffffffu, ls0, 2);
        ls1 += __shfl_xor_sync(0xffffffffu, ls1, 1);
        ls1 += __shfl_xor_sync(0xffffffffu, ls1, 2);
        const size_t rb = (size_t)b*TT + t0;
        uint32_t* pb = g_parth + (size_t)e*(MM*HH/2);
        #pragma unroll
        for (int jc = 0; jc < 8; jc++) {
            int c = 8*jc + 2*t;
            pb[((rb + R0)*HH + c) >> 1] = packh2(o[jc][0], o[jc][1]);
            pb[((rb + R1)*HH + c) >> 1] = packh2(o[jc][2], o[jc][3]);
        }
        if (t == 0) {
            g_lpart[e*MM + rb + R0] = ls0;
            g_lpart[e*MM + rb + R1] = ls1;
        }
        __syncthreads();
    }
}

// ---------------------------------------------------------------------------
// combine 4-way fp16 split-K partials: out = sum(O_e) / sum(l_e)
// each thread: 8 output floats (uint4 per partial, MLP=4x independent)
// ---------------------------------------------------------------------------
__global__ __launch_bounds__(256) void combine_kernel(float* __restrict__ out) {
    int gid = blockIdx.x * 256 + threadIdx.x;      // 0 .. MM*HH/8-1
    int m = gid >> 3;
    float l = 0.f;
    float a[8];
    #pragma unroll
    for (int i = 0; i < 8; i++) a[i] = 0.f;
    #pragma unroll
    for (int k = 0; k < 4; k++) {
        uint4 u = *(const uint4*)&g_parth[(size_t)k*(MM*HH/2) + (size_t)gid*4];
        float2 f;
        f = __half22float2(*(__half2*)&u.x); a[0] += f.x; a[1] += f.y;
        f = __half22float2(*(__half2*)&u.y); a[2] += f.x; a[3] += f.y;
        f = __half22float2(*(__half2*)&u.z); a[4] += f.x; a[5] += f.y;
        f = __half22float2(*(__half2*)&u.w); a[6] += f.x; a[7] += f.y;
        l += g_lpart[k*MM + m];
    }
    float inv = 1.f / l;
    float4 o0 = make_float4(a[0]*inv, a[1]*inv, a[2]*inv, a[3]*inv);
    float4 o1 = make_float4(a[4]*inv, a[5]*inv, a[6]*inv, a[7]*inv);
    *(float4*)&out[(size_t)gid*8]     = o0;
    *(float4*)&out[(size_t)gid*8 + 4] = o1;
}

extern "C" void kernel_launch(void* const* d_in, const int* in_sizes, int n_in,
                              void* d_out, int out_size) {
    (void)in_sizes; (void)n_in; (void)out_size;
    const float* x  = (const float*)d_in[0];
    const float* Wq = (const float*)d_in[1];
    const float* Wk = (const float*)d_in[2];
    const float* Wv = (const float*)d_in[3];
    float* out = (float*)d_out;

    wconv_kernel<<<(3*HH*(CC/2))/256, 256>>>(Wq, Wk, Wv);

    cudaFuncSetAttribute(qkv_proj, cudaFuncAttributeMaxDynamicSharedMemorySize, QKV_SMEM);
    qkv_proj<<<dim3(MM/128, 1), 512, QKV_SMEM>>>(x);

    cudaFuncSetAttribute(attn_kernel, cudaFuncAttributeMaxDynamicSharedMemorySize, ATTN_SMEM);
    attn_kernel<<<dim3(128, BB), 128, ATTN_SMEM>>>();

    combine_kernel<<<(MM*HH/8)/256, 256>>>(out);
}

// round 17
// speedup vs baseline: 1.0495x; 1.0495x over previous
#include <cuda_runtime.h>
#include <cuda_bf16.h>
#include <cuda_fp16.h>
#include <stdint.h>

#define BB 4
#define TT 4096
#define CC 1024
#define HH 64
#define MM (BB*TT)

// scratch (allocation-free rule -> device globals)
__device__ unsigned short g_q[MM*HH];           // fp16 q * 1/32
__device__ unsigned short g_k[MM*HH];           // fp16 k
__device__ unsigned short g_vt[BB*HH*TT];       // fp16 V^T  [b][h][t]
__device__ uint32_t g_w16[3*HH*(CC/2)];         // fp16 W^T [mat][n][k-pairs]
__device__ float g_part[4u*MM*HH];              // fp32 split-K O partials (4-way)
__device__ float g_lpart[4*MM];                 // split-K l partials

// ---------------------------------------------------------------------------
// helpers
// ---------------------------------------------------------------------------
__device__ __forceinline__ void mma16h(float* d,
    uint32_t a0, uint32_t a1, uint32_t a2, uint32_t a3, uint32_t b0, uint32_t b1) {
    asm volatile(
        "mma.sync.aligned.m16n8k16.row.col.f32.f16.f16.f32 "
        "{%0,%1,%2,%3},{%4,%5,%6,%7},{%8,%9},{%0,%1,%2,%3};"
        : "+f"(d[0]), "+f"(d[1]), "+f"(d[2]), "+f"(d[3])
        : "r"(a0), "r"(a1), "r"(a2), "r"(a3), "r"(b0), "r"(b1));
}
__device__ __forceinline__ uint32_t packh2(float lo, float hi) {  // {lo, hi}
    uint32_t r; asm("cvt.rn.f16x2.f32 %0, %1, %2;" : "=r"(r) : "f"(hi), "f"(lo));
    return r;
}
__device__ __forceinline__ uint32_t smem_u32(const void* p) {
    uint32_t a;
    asm("{ .reg .u64 t; cvta.to.shared.u64 t, %1; cvt.u32.u64 %0, t; }" : "=r"(a) : "l"(p));
    return a;
}
__device__ __forceinline__ void cp16(uint32_t dst, const void* src) {
    asm volatile("cp.async.cg.shared.global [%0], [%1], 16;" :: "r"(dst), "l"(src));
}
#define CP_COMMIT() asm volatile("cp.async.commit_group;" ::: "memory")
#define CP_WAIT1()  asm volatile("cp.async.wait_group 1;" ::: "memory")
#define CP_WAIT0()  asm volatile("cp.async.wait_group 0;" ::: "memory")

// ---------------------------------------------------------------------------
// W pre-convert: g_w16[mat][n][k2] = fp16 pair {W[2k2][n], W[2k2+1][n]}
// ---------------------------------------------------------------------------
__global__ __launch_bounds__(256) void wconv_kernel(const float* __restrict__ Wq,
                                                    const float* __restrict__ Wk,
                                                    const float* __restrict__ Wv) {
    int u = blockIdx.x * 256 + threadIdx.x;      // 0 .. 3*64*512-1
    int k2 = u & 511, n = (u >> 9) & 63, mat = u >> 15;
    const float* W = (mat == 0) ? Wq : (mat == 1) ? Wk : Wv;
    float f0 = W[(size_t)(2*k2)*HH + n];
    float f1 = W[(size_t)(2*k2 + 1)*HH + n];
    g_w16[u] = packh2(f0, f1);
}

// ---------------------------------------------------------------------------
// Fused QKV projection (round-15, unchanged), fp16 m16n8k16, 256 threads.
// x fp32 double-buffered via cp.async (A-frags via LDS.64+packh2);
// W fp16 double-buffered via cp.async from g_w16.
// ---------------------------------------------------------------------------
#define XSTR 68
#define W16STR 36
#define QSM_X   0                              // 2 x 128*68*4 = 69632
#define QSM_W   (2*128*XSTR*4)                 // 2 x 192*36*4 = 55296
static const int QKV_SMEM = QSM_W + 2*192*W16STR*4;   // 124928

__device__ __forceinline__ void x_prefetch(uint32_t smb, int buf,
                                           const float* __restrict__ x,
                                           int row0, int k0g) {
    const int tid = threadIdx.x;
    const uint32_t base = smb + QSM_X + buf*(128*XSTR*4);
    #pragma unroll
    for (int it = 0; it < 8; it++) {
        int u = tid + 256*it;
        int r = u >> 4, c = (u & 15) << 2;
        cp16(base + (uint32_t)(r*XSTR + c)*4, &x[(size_t)(row0 + r)*CC + k0g + c]);
    }
}
__device__ __forceinline__ void w_prefetch(uint32_t smb, int buf, int k0g) {
    const int tid = threadIdx.x;
    const uint32_t base = smb + QSM_W + buf*(192*W16STR*4);
    // 192 rows (q 0-63, k 64-127, v 128-191) x 32 u32 (=128B) per row
    #pragma unroll
    for (int it = 0; it < 6; it++) {
        int u = tid + 256*it;             // 0..1535
        int r = u >> 3, q = u & 7;
        cp16(base + (uint32_t)(r*W16STR + q*4)*4,
             &g_w16[(size_t)r*512 + (k0g >> 1) + q*4]);
    }
}

__global__ __launch_bounds__(256, 1) void qkv_proj(const float* __restrict__ x) {
    extern __shared__ uint32_t smq[];
    const uint32_t smb = smem_u32(smq);

    const int tid = threadIdx.x;
    const int w = tid >> 5, lane = tid & 31, g = lane >> 2, t = lane & 3;
    const int row0 = blockIdx.x * 128;

    float aq[8][4], ak[8][4], av[8][4];
    #pragma unroll
    for (int j = 0; j < 8; j++)
        #pragma unroll
        for (int i = 0; i < 4; i++) { aq[j][i] = 0.f; ak[j][i] = 0.f; av[j][i] = 0.f; }

    x_prefetch(smb, 0, x, row0, 0);
    w_prefetch(smb, 0, 0);
    CP_COMMIT();

    for (int c16 = 0; c16 < 16; c16++) {
        const int k0g = c16 * 64;
        __syncthreads();                  // prev chunk compute done (guards both bufs)
        if (c16 + 1 < 16) {
            x_prefetch(smb, (c16 + 1) & 1, x, row0, k0g + 64);
            w_prefetch(smb, (c16 + 1) & 1, k0g + 64);
            CP_COMMIT();
            CP_WAIT1();
        } else {
            CP_WAIT0();
        }
        __syncthreads();

        const float* Xr = (const float*)(smq + (QSM_X/4) + (c16 & 1)*(128*XSTR));
        const uint32_t* Ws = smq + (QSM_W/4) + (c16 & 1)*(192*W16STR);
        const int ra = (16*w + g)*XSTR, rb = ra + 8*XSTR;
        #pragma unroll
        for (int kk = 0; kk < 4; kk++) {
            const int k0 = kk * 16;
            float2 f00 = *(const float2*)&Xr[ra + k0 + 2*t];
            float2 f10 = *(const float2*)&Xr[rb + k0 + 2*t];
            float2 f01 = *(const float2*)&Xr[ra + k0 + 2*t + 8];
            float2 f11 = *(const float2*)&Xr[rb + k0 + 2*t + 8];
            uint32_t a0 = packh2(f00.x, f00.y), a1 = packh2(f10.x, f10.y);
            uint32_t a2 = packh2(f01.x, f01.y), a3 = packh2(f11.x, f11.y);
            #pragma unroll
            for (int j = 0; j < 8; j++) {
                const int rq = (8*j + g)*W16STR + 8*kk + t;
                mma16h(aq[j], a0, a1, a2, a3, Ws[rq],                   Ws[rq + 4]);
                mma16h(ak[j], a0, a1, a2, a3, Ws[rq + 64*W16STR],       Ws[rq + 64*W16STR + 4]);
                mma16h(av[j], a0, a1, a2, a3, Ws[rq + 128*W16STR],      Ws[rq + 128*W16STR + 4]);
            }
        }
    }

    // epilogue: q (scaled 1/32, exact) and k as packed fp16 pairs
    const int lr0 = 16*w + g;
    const size_t r0 = (size_t)(row0 + lr0), r1 = r0 + 8;
    #pragma unroll
    for (int j = 0; j < 8; j++) {
        int c = 8*j + 2*t;
        *(uint32_t*)&g_q[r0*HH + c] = packh2(aq[j][0]*0.03125f, aq[j][1]*0.03125f);
        *(uint32_t*)&g_q[r1*HH + c] = packh2(aq[j][2]*0.03125f, aq[j][3]*0.03125f);
        *(uint32_t*)&g_k[r0*HH + c] = packh2(ak[j][0], ak[j][1]);
        *(uint32_t*)&g_k[r1*HH + c] = packh2(ak[j][2], ak[j][3]);
    }
    // stage v as fp16 bits (one per u32 slot), write transposed [b][h][t]
    __syncthreads();
    uint32_t* Vstg = smq;   // x buffers area, stride 68
    #pragma unroll
    for (int j = 0; j < 8; j++) {
        int c = 8*j + 2*t;
        Vstg[lr0*XSTR + c]         = (uint32_t)__half_as_ushort(__float2half_rn(av[j][0]));
        Vstg[lr0*XSTR + c + 1]     = (uint32_t)__half_as_ushort(__float2half_rn(av[j][1]));
        Vstg[(lr0+8)*XSTR + c]     = (uint32_t)__half_as_ushort(__float2half_rn(av[j][2]));
        Vstg[(lr0+8)*XSTR + c + 1] = (uint32_t)__half_as_ushort(__float2half_rn(av[j][3]));
    }
    __syncthreads();
    {
        int hh = tid >> 2, tp = tid & 3;
        int bB = row0 / TT, tt0 = row0 % TT;
        size_t basei = ((size_t)bB*HH + hh)*TT + tt0;
        #pragma unroll
        for (int s = 0; s < 32; s += 2) {
            int tt = tp*32 + s;
            uint32_t w0 = Vstg[tt*XSTR + hh], w1 = Vstg[(tt+1)*XSTR + hh];
            *(uint32_t*)&g_vt[basei + tt] = (w0 & 0xffffu) | (w1 << 16);
        }
    }
}

// ---------------------------------------------------------------------------
// Flash attention (round-15, unchanged): BR=64, 128 threads, 4 CTAs/SM,
// fp16 Q/K/V throughout, P fp16 in registers, 4-way split-K, fp32 partials.
// ---------------------------------------------------------------------------
#define KSTR2 36
#define VTSTR 36
#define SMK   0
#define SMV   (SMK + 2*64*KSTR2*4)
#define ATTN_SMEM (SMV + 2*64*VTSTR*4)      // 36864

__device__ __forceinline__ void kv_prefetch(uint32_t smb, int buf, int b, int kt0) {
    const int tid = threadIdx.x;
    const uint32_t kb = smb + SMK + buf*(64*KSTR2*4);
    const uint32_t vb = smb + SMV + buf*(64*VTSTR*4);
    #pragma unroll
    for (int it = 0; it < 4; it++) {
        int u = tid + 128*it, r = u >> 3, q = u & 7;
        cp16(kb + (uint32_t)(r*KSTR2 + q*4)*4,
             (const char*)&g_k[((size_t)(b*TT + kt0 + r))*HH] + q*16);
    }
    #pragma unroll
    for (int it = 0; it < 4; it++) {
        int u = tid + 128*it, h = u >> 3, q = u & 7;
        cp16(vb + (uint32_t)(h*VTSTR + q*4)*4,
             (const char*)&g_vt[((size_t)(b*HH + h))*TT + kt0] + q*16);
    }
}

__global__ __launch_bounds__(128, 4) void attn_kernel() {
    extern __shared__ char sm[];
    const uint32_t smb = smem_u32(sm);
    const int tid = threadIdx.x, w = tid >> 5, lane = tid & 31;
    const int g = lane >> 2, t = lane & 3;
    const int b = blockIdx.y, e = blockIdx.x & 3, p = blockIdx.x >> 2;
    const int R0 = 16*w + g, R1 = R0 + 8;

    for (int ti = 0; ti < 2; ti++) {
        const int qt = ti ? 63 - p : p;
        const int t0 = qt * 64;
        const int n = (qt >= e) ? ((qt - e) >> 2) + 1 : 0;

        float o[8][4];
        #pragma unroll
        for (int j = 0; j < 8; j++)
            #pragma unroll
            for (int i = 0; i < 4; i++) o[j][i] = 0.f;
        float ls0 = 0.f, ls1 = 0.f;

        if (n > 0) {
            uint32_t* Pst = (uint32_t*)(sm + SMK);
            #pragma unroll
            for (int it = 0; it < 4; it++) {
                int u = tid + 128*it, r = u >> 3, q = u & 7;
                cp16(smb + SMK + (uint32_t)(r*KSTR2 + q*4)*4,
                     (const char*)&g_q[((size_t)(b*TT + t0 + r))*HH] + q*16);
            }
            CP_COMMIT(); CP_WAIT0();
            __syncthreads();
            uint32_t qa[4][4];
            #pragma unroll
            for (int kk = 0; kk < 4; kk++) {
                qa[kk][0] = Pst[R0*KSTR2 + 8*kk + t];
                qa[kk][1] = Pst[R1*KSTR2 + 8*kk + t];
                qa[kk][2] = Pst[R0*KSTR2 + 8*kk + t + 4];
                qa[kk][3] = Pst[R1*KSTR2 + 8*kk + t + 4];
            }
            __syncthreads();
            kv_prefetch(smb, 0, b, e*64);
            CP_COMMIT();

            for (int j = 0; j < n; j++) {
                const int kb = e + 4*j;
                const int kt0 = kb * 64;
                if (j + 1 < n) { kv_prefetch(smb, (j + 1) & 1, b, kt0 + 256); CP_COMMIT(); CP_WAIT1(); }
                else           { CP_WAIT0(); }
                __syncthreads();
                const uint32_t* Ks = (const uint32_t*)(sm + SMK + (j & 1)*(64*KSTR2*4));
                const uint32_t* Vs = (const uint32_t*)(sm + SMV + (j & 1)*(64*VTSTR*4));

                float s[8][4];
                #pragma unroll
                for (int jc = 0; jc < 8; jc++)
                    #pragma unroll
                    for (int i = 0; i < 4; i++) s[jc][i] = 0.f;
                #pragma unroll
                for (int kk = 0; kk < 4; kk++) {
                    #pragma unroll
                    for (int jc = 0; jc < 8; jc++)
                        mma16h(s[jc], qa[kk][0], qa[kk][1], qa[kk][2], qa[kk][3],
                               Ks[(8*jc + g)*KSTR2 + 8*kk + t],
                               Ks[(8*jc + g)*KSTR2 + 8*kk + t + 4]);
                }

                const int last = (kb == qt);
                const int r0g = t0 + R0, r1g = t0 + R1;
                #pragma unroll
                for (int kk = 0; kk < 4; kk++) {
                    uint32_t ah[4];
                    #pragma unroll
                    for (int hhh = 0; hhh < 2; hhh++) {
                        const int jc = 2*kk + hhh;
                        const int key = kt0 + 8*jc + 2*t;
                        float p00, p01, p10, p11;
                        if (last) {
                            p00 = (key     <= r0g) ? __expf(s[jc][0]) : 0.f;
                            p01 = (key + 1 <= r0g) ? __expf(s[jc][1]) : 0.f;
                            p10 = (key     <= r1g) ? __expf(s[jc][2]) : 0.f;
                            p11 = (key + 1 <= r1g) ? __expf(s[jc][3]) : 0.f;
                        } else {
                            p00 = __expf(s[jc][0]); p01 = __expf(s[jc][1]);
                            p10 = __expf(s[jc][2]); p11 = __expf(s[jc][3]);
                        }
                        ls0 += p00 + p01; ls1 += p10 + p11;
                        ah[2*hhh]     = packh2(p00, p01);
                        ah[2*hhh + 1] = packh2(p10, p11);
                    }
                    #pragma unroll
                    for (int jc = 0; jc < 8; jc++) {
                        uint32_t v0 = Vs[(8*jc + g)*VTSTR + 8*kk + t];
                        uint32_t v1 = Vs[(8*jc + g)*VTSTR + 8*kk + t + 4];
                        mma16h(o[jc], ah[0], ah[1], ah[2], ah[3], v0, v1);
                    }
                }
                __syncthreads();
            }
        }

        ls0 += __shfl_xor_sync(0xffffffffu, ls0, 1);
        ls0 += __shfl_xor_sync(0xffffffffu, ls0, 2);
        ls1 += __shfl_xor_sync(0xffffffffu, ls1, 1);
        ls1 += __shfl_xor_sync(0xffffffffu, ls1, 2);
        const size_t rb = (size_t)b*TT + t0;
        float* pbase = g_part + (size_t)e*MM*HH;
        #pragma unroll
        for (int jc = 0; jc < 8; jc++) {
            int c = 8*jc + 2*t;
            *(float2*)&pbase[(rb + R0)*HH + c] = make_float2(o[jc][0], o[jc][1]);
            *(float2*)&pbase[(rb + R1)*HH + c] = make_float2(o[jc][2], o[jc][3]);
        }
        if (t == 0) {
            g_lpart[e*MM + rb + R0] = ls0;
            g_lpart[e*MM + rb + R1] = ls1;
        }
        __syncthreads();
    }
}

// ---------------------------------------------------------------------------
// combine 4-way fp32 split-K partials, 8 floats/thread (MLP = 8 LDG.128):
// out = sum(O_e) / sum(l_e)
// ---------------------------------------------------------------------------
__global__ __launch_bounds__(256) void combine_kernel(float* __restrict__ out) {
    int gid = blockIdx.x * 256 + threadIdx.x;   // 0 .. MM*HH/8-1
    int m = gid >> 3;
    float l = 0.f;
    float4 a0 = make_float4(0.f, 0.f, 0.f, 0.f);
    float4 a1 = make_float4(0.f, 0.f, 0.f, 0.f);
    #pragma unroll
    for (int k = 0; k < 4; k++) {
        const float* p = &g_part[(size_t)k*MM*HH + (size_t)gid*8];
        float4 c0 = *(const float4*)p;
        float4 c1 = *(const float4*)(p + 4);
        a0.x += c0.x; a0.y += c0.y; a0.z += c0.z; a0.w += c0.w;
        a1.x += c1.x; a1.y += c1.y; a1.z += c1.z; a1.w += c1.w;
        l += g_lpart[k*MM + m];
    }
    float inv = 1.f / l;
    *(float4*)&out[(size_t)gid*8]     = make_float4(a0.x*inv, a0.y*inv, a0.z*inv, a0.w*inv);
    *(float4*)&out[(size_t)gid*8 + 4] = make_float4(a1.x*inv, a1.y*inv, a1.z*inv, a1.w*inv);
}

extern "C" void kernel_launch(void* const* d_in, const int* in_sizes, int n_in,
                              void* d_out, int out_size) {
    (void)in_sizes; (void)n_in; (void)out_size;
    const float* x  = (const float*)d_in[0];
    const float* Wq = (const float*)d_in[1];
    const float* Wk = (const float*)d_in[2];
    const float* Wv = (const float*)d_in[3];
    float* out = (float*)d_out;

    wconv_kernel<<<(3*HH*(CC/2))/256, 256>>>(Wq, Wk, Wv);

    cudaFuncSetAttribute(qkv_proj, cudaFuncAttributeMaxDynamicSharedMemorySize, QKV_SMEM);
    qkv_proj<<<dim3(MM/128, 1), 256, QKV_SMEM>>>(x);

    cudaFuncSetAttribute(attn_kernel, cudaFuncAttributeMaxDynamicSharedMemorySize, ATTN_SMEM);
    attn_kernel<<<dim3(128, BB), 128, ATTN_SMEM>>>();

    combine_kernel<<<(MM*HH/8)/256, 256>>>(out);
}